// round 9
// baseline (speedup 1.0000x reference)
#include <cuda_runtime.h>
#include <cuda_bf16.h>

#define NNUC  8
#define NCHI  8
#define NU    8
#define WLK   4      // walkers per block, depth-2 pipelined loop

typedef unsigned long long u64;

// ---- f32x2 packed helpers (Blackwell) ----
__device__ __forceinline__ u64 pk2(float lo, float hi) {
    u64 r; asm("mov.b64 %0, {%1, %2};" : "=l"(r) : "f"(lo), "f"(hi)); return r;
}
__device__ __forceinline__ void upk2(u64 v, float& lo, float& hi) {
    asm("mov.b64 {%0, %1}, %2;" : "=f"(lo), "=f"(hi) : "l"(v));
}
__device__ __forceinline__ u64 fma2(u64 a, u64 b, u64 c) {
    u64 d; asm("fma.rn.f32x2 %0, %1, %2, %3;" : "=l"(d) : "l"(a), "l"(b), "l"(c)); return d;
}
__device__ __forceinline__ u64 mul2(u64 a, u64 b) {
    u64 d; asm("mul.rn.f32x2 %0, %1, %2;" : "=l"(d) : "l"(a), "l"(b)); return d;
}

// Flat float4-chunk indices (i*8 + c) of the 136 chunks touching the strict
// upper triangle of the 32x32 elec matrix.
__constant__ unsigned char UPPER_TAB_C[136] = {
    0,1,2,3,4,5,6,7,
    8,9,10,11,12,13,14,15,
    16,17,18,19,20,21,22,23,
    25,26,27,28,29,30,31,
    33,34,35,36,37,38,39,
    41,42,43,44,45,46,47,
    49,50,51,52,53,54,55,
    58,59,60,61,62,63,
    66,67,68,69,70,71,
    74,75,76,77,78,79,
    82,83,84,85,86,87,
    91,92,93,94,95,
    99,100,101,102,103,
    107,108,109,110,111,
    115,116,117,118,119,
    124,125,126,127,
    132,133,134,135,
    140,141,142,143,
    148,149,150,151,
    157,158,159,
    165,166,167,
    173,174,175,
    181,182,183,
    190,191,
    198,199,
    206,207,
    214,215,
    223,
    231,
    239,
    247
};

__global__ __launch_bounds__(224, 6)
void jastrow_kernel(
    const float4* __restrict__ elec4,   // [B, 256]
    const float4* __restrict__ nuc4,    // [B, 64]
    const float* __restrict__ alpha,    // [8]
    const float* __restrict__ beta,     // [3, 8]
    const float* __restrict__ Zarr,     // [8]
    const float* __restrict__ Lchi,     // [3]
    const float* __restrict__ Lu_p,     // [1]
    const int*   __restrict__ type_idx, // [8]
    float* __restrict__ out)            // [B]
{
    __shared__ u64 s_a2[NU];            // alpha[q] broadcast-packed
    __shared__ u64 s_ss2, s_sd2;
    __shared__ u64 s_hi2[4][NCHI - 1];  // beta[1..7]/8 per nucleus pair
    __shared__ u64 s_c02[4];
    __shared__ u64 s_lin2[4];
    __shared__ float s_L[NNUC];
    __shared__ float s_Lu;
    __shared__ float s_part[WLK][7];

    const int t    = threadIdx.x;       // slot 0..223
    const int lane = t & 31;
    const int warp = t >> 5;            // 0..6
    const int b0   = blockIdx.x * WLK;

    // ---- one-time coefficient setup ----
    if (t < NNUC) s_L[t] = Lchi[type_idx[t]];
    if (t >= 8 && t < 16) {
        int q = t - 8;
        float a = alpha[q];
        s_a2[q] = pk2(a, a);
    }
    if (t == 16) {
        float Lu = Lu_p[0];
        s_Lu = Lu;
        float a0 = alpha[0];
        float negL3 = -(Lu * Lu * Lu);
        float ss = 0.25f / negL3 + a0 * 3.0f / Lu;
        float sd = 0.50f / negL3 + a0 * 3.0f / Lu;
        s_ss2 = pk2(ss, ss);
        s_sd2 = pk2(sd, sd);
    }
    if (t >= 32 && t < 32 + 28) {
        int k = t - 32, pr = k / 7, q = k % 7;
        int m0 = 2 * pr, m1 = m0 + 1;
        int ty0 = type_idx[m0], ty1 = type_idx[m1];
        s_hi2[pr][q] = pk2(beta[ty0 * NCHI + q + 1] * 0.125f,
                           beta[ty1 * NCHI + q + 1] * 0.125f);
    }
    if (t >= 64 && t < 68) {
        int pr = t - 64;
        int m0 = 2 * pr, m1 = m0 + 1;
        int ty0 = type_idx[m0], ty1 = type_idx[m1];
        float La = Lchi[ty0], Lb = Lchi[ty1];
        float b00 = beta[ty0 * NCHI], b01 = beta[ty1 * NCHI];
        float lin0 = (-Zarr[m0] / (-(La * La * La)) + b00 * 3.0f / La) * 0.125f;
        float lin1 = (-Zarr[m1] / (-(Lb * Lb * Lb)) + b01 * 3.0f / Lb) * 0.125f;
        s_c02[pr]  = pk2(b00 * 0.125f, b01 * 0.125f);
        s_lin2[pr] = pk2(lin0, lin1);
    }
    __syncthreads();

    if (t < 64) {
        // ================= nuc branch (warps 0,1) =================
        const int pr0 = (t & 1) * 2;
        const int mb  = (t & 1) * 4;
        const float L0 = s_L[mb], L1 = s_L[mb + 1], L2 = s_L[mb + 2], L3 = s_L[mb + 3];
        // hoist coefficients to registers
        u64 hA[7], hB[7];
        #pragma unroll
        for (int q = 0; q < 7; ++q) { hA[q] = s_hi2[pr0][q]; hB[q] = s_hi2[pr0 + 1][q]; }
        const u64 c0A = s_c02[pr0], c0B = s_c02[pr0 + 1];
        const u64 lnA = s_lin2[pr0], lnB = s_lin2[pr0 + 1];

        const float4* base = nuc4 + (size_t)b0 * 64 + t;
        float4 cur = __ldg(base);

        #pragma unroll
        for (int w = 0; w < WLK; ++w) {
            float4 nxt;
            if (w + 1 < WLK) nxt = __ldg(base + (size_t)(w + 1) * 64);

            float rc0 = fminf(cur.x, L0), rc1 = fminf(cur.y, L1);
            float rc2 = fminf(cur.z, L2), rc3 = fminf(cur.w, L3);
            u64 rA = pk2(rc0, rc1), rB = pk2(rc2, rc3);
            u64 dA = pk2(rc0 - L0, rc1 - L1), dB = pk2(rc2 - L2, rc3 - L3);
            u64 envA = mul2(mul2(dA, dA), dA);
            u64 envB = mul2(mul2(dB, dB), dB);
            u64 pA = hA[6], pB = hB[6];
            #pragma unroll
            for (int q = 5; q >= 0; --q) {
                pA = fma2(pA, rA, hA[q]);
                pB = fma2(pB, rB, hB[q]);
            }
            u64 rA2 = mul2(rA, rA), rB2 = mul2(rB, rB);
            pA = fma2(pA, rA2, fma2(lnA, rA, c0A));
            pB = fma2(pB, rB2, fma2(lnB, rB, c0B));
            u64 acc2 = fma2(envB, pB, mul2(envA, pA));

            float aLo, aHi;
            upk2(acc2, aLo, aHi);
            float acc = aLo + aHi;
            #pragma unroll
            for (int off = 16; off > 0; off >>= 1)
                acc += __shfl_down_sync(0xffffffffu, acc, off);
            if (lane == 0) s_part[w][warp] = acc;

            cur = nxt;
        }
    } else {
        // ================= elec branch (warps 2..6) =================
        int k = t - 64; if (k > 135) k = 135;
        const int chunk = UPPER_TAB_C[k];
        const int ei = chunk >> 3, jb = (chunk & 7) * 4;
        const bool dummy = (t >= 200);
        const float Lu = s_Lu;
        // bias: -inf for live elements (no-op), Lu for masked (forces env=0)
        float bias0 = (!dummy && jb + 0 > ei) ? -3e38f : Lu;
        float bias1 = (!dummy && jb + 1 > ei) ? -3e38f : Lu;
        float bias2 = (!dummy && jb + 2 > ei) ? -3e38f : Lu;
        float bias3 = (!dummy && jb + 3 > ei) ? -3e38f : Lu;
        const u64 slope2 = (((ei < 16) == (jb < 16)) ? s_ss2 : s_sd2);
        // hoist alpha to registers
        u64 a[NU];
        #pragma unroll
        for (int q = 0; q < NU; ++q) a[q] = s_a2[q];

        const float4* base = elec4 + (size_t)b0 * 256 + chunk;
        float4 cur = __ldg(base);

        #pragma unroll
        for (int w = 0; w < WLK; ++w) {
            float4 nxt;
            if (w + 1 < WLK) nxt = __ldg(base + (size_t)(w + 1) * 256);

            float rc0 = fmaxf(fminf(cur.x, Lu), bias0);
            float rc1 = fmaxf(fminf(cur.y, Lu), bias1);
            float rc2 = fmaxf(fminf(cur.z, Lu), bias2);
            float rc3 = fmaxf(fminf(cur.w, Lu), bias3);
            u64 rA = pk2(rc0, rc1), rB = pk2(rc2, rc3);
            u64 dA = pk2(rc0 - Lu, rc1 - Lu), dB = pk2(rc2 - Lu, rc3 - Lu);
            u64 envA = mul2(mul2(dA, dA), dA);
            u64 envB = mul2(mul2(dB, dB), dB);
            u64 pA = a[NU - 1], pB = a[NU - 1];
            #pragma unroll
            for (int q = NU - 2; q >= 1; --q) {
                pA = fma2(pA, rA, a[q]);
                pB = fma2(pB, rB, a[q]);
            }
            u64 rA2 = mul2(rA, rA), rB2 = mul2(rB, rB);
            pA = fma2(pA, rA2, fma2(slope2, rA, a[0]));
            pB = fma2(pB, rB2, fma2(slope2, rB, a[0]));
            u64 acc2 = fma2(envB, pB, mul2(envA, pA));

            float aLo, aHi;
            upk2(acc2, aLo, aHi);
            float acc = aLo + aHi;
            #pragma unroll
            for (int off = 16; off > 0; off >>= 1)
                acc += __shfl_down_sync(0xffffffffu, acc, off);
            if (lane == 0) s_part[w][warp] = acc;

            cur = nxt;
        }
    }

    __syncthreads();
    if (t < WLK) {
        float s = 0.0f;
        #pragma unroll
        for (int q = 0; q < 7; ++q) s += s_part[t][q];
        out[b0 + t] = s;
    }
}

extern "C" void kernel_launch(void* const* d_in, const int* in_sizes, int n_in,
                              void* d_out, int out_size)
{
    const float4* elec  = (const float4*)d_in[0];
    const float4* nuc   = (const float4*)d_in[1];
    const float* alpha  = (const float*)d_in[2];
    const float* beta   = (const float*)d_in[3];
    const float* Z      = (const float*)d_in[4];
    const float* Lchi   = (const float*)d_in[5];
    const float* Lu     = (const float*)d_in[6];
    const int*   tidx   = (const int*)  d_in[7];
    float* out = (float*)d_out;

    int B = in_sizes[1] / (32 * NNUC);   // 4096

    jastrow_kernel<<<B / WLK, 224>>>(elec, nuc, alpha, beta, Z, Lchi, Lu, tidx, out);
}

// round 10
// speedup vs baseline: 1.0050x; 1.0050x over previous
#include <cuda_runtime.h>
#include <cstdint>

#define NNUC  8
#define NCHI  8
#define NU    8
#define WPB   8      // walkers per block (one warp each)

typedef unsigned long long u64;

// ---- f32x2 packed helpers ----
__device__ __forceinline__ u64 pk2(float lo, float hi) {
    u64 r; asm("mov.b64 %0, {%1, %2};" : "=l"(r) : "f"(lo), "f"(hi)); return r;
}
__device__ __forceinline__ void upk2(u64 v, float& lo, float& hi) {
    asm("mov.b64 {%0, %1}, %2;" : "=f"(lo), "=f"(hi) : "l"(v));
}
__device__ __forceinline__ u64 fma2(u64 a, u64 b, u64 c) {
    u64 d; asm("fma.rn.f32x2 %0, %1, %2, %3;" : "=l"(d) : "l"(a), "l"(b), "l"(c)); return d;
}
__device__ __forceinline__ u64 mul2(u64 a, u64 b) {
    u64 d; asm("mul.rn.f32x2 %0, %1, %2;" : "=l"(d) : "l"(a), "l"(b)); return d;
}

__device__ __forceinline__ uint32_t smem_u32(const void* p) {
    uint32_t a;
    asm("{ .reg .u64 t; cvta.to.shared.u64 t, %1; cvt.u32.u64 %0, t; }" : "=r"(a) : "l"(p));
    return a;
}

// Flat float4-chunk indices of the 136 upper-triangle chunks of the 32x32 elec matrix.
__constant__ unsigned char UPPER_TAB_C[136] = {
    0,1,2,3,4,5,6,7,
    8,9,10,11,12,13,14,15,
    16,17,18,19,20,21,22,23,
    25,26,27,28,29,30,31,
    33,34,35,36,37,38,39,
    41,42,43,44,45,46,47,
    49,50,51,52,53,54,55,
    58,59,60,61,62,63,
    66,67,68,69,70,71,
    74,75,76,77,78,79,
    82,83,84,85,86,87,
    91,92,93,94,95,
    99,100,101,102,103,
    107,108,109,110,111,
    115,116,117,118,119,
    124,125,126,127,
    132,133,134,135,
    140,141,142,143,
    148,149,150,151,
    157,158,159,
    165,166,167,
    173,174,175,
    181,182,183,
    190,191,
    198,199,
    206,207,
    214,215,
    223,
    231,
    239,
    247
};

__global__ __launch_bounds__(256)
void jastrow_kernel(
    const char* __restrict__ elec_g,    // [B][4096 bytes]
    const char* __restrict__ nuc_g,     // [B][1024 bytes]
    const float* __restrict__ alpha,    // [8]
    const float* __restrict__ beta,     // [3, 8]
    const float* __restrict__ Zarr,     // [8]
    const float* __restrict__ Lchi,     // [3]
    const float* __restrict__ Lu_p,     // [1]
    const int*   __restrict__ type_idx, // [8]
    float* __restrict__ out)            // [B]
{
    __shared__ __align__(128) char s_nuc[WPB * 1024];    // 8 KB
    __shared__ __align__(128) char s_elec[WPB * 4096];   // 32 KB
    __shared__ __align__(16)  float4 s_bias[160];        // elec clamp biases (136 live + dummies)
    __shared__ u64  s_slope[160];
    __shared__ u64  s_hi2[4][NCHI - 1];                  // beta[1..7]/8 per nucleus pair
    __shared__ u64  s_c02[4], s_lin2[4];
    __shared__ float s_L[NNUC];
    __shared__ __align__(8) u64 s_mbar;

    const int t    = threadIdx.x;
    const int lane = t & 31;
    const int w    = t >> 5;            // warp = walker within block
    const int g0   = blockIdx.x * WPB;

    const uint32_t mbar = smem_u32(&s_mbar);

    // ---- init mbarrier, then issue the bulk copies (one thread) ----
    if (t == 0) {
        asm volatile("mbarrier.init.shared.b64 [%0], 1;" :: "r"(mbar) : "memory");
    }
    __syncthreads();
    if (t == 0) {
        asm volatile("mbarrier.arrive.expect_tx.shared.b64 _, [%0], %1;"
                     :: "r"(mbar), "r"((uint32_t)(WPB * 1024 + WPB * 4096)) : "memory");
        asm volatile("cp.async.bulk.shared::cluster.global.mbarrier::complete_tx::bytes "
                     "[%0], [%1], %2, [%3];"
                     :: "r"(smem_u32(s_nuc)), "l"(nuc_g + (size_t)g0 * 1024),
                        "r"((uint32_t)(WPB * 1024)), "r"(mbar) : "memory");
        asm volatile("cp.async.bulk.shared::cluster.global.mbarrier::complete_tx::bytes "
                     "[%0], [%1], %2, [%3];"
                     :: "r"(smem_u32(s_elec)), "l"(elec_g + (size_t)g0 * 4096),
                        "r"((uint32_t)(WPB * 4096)), "r"(mbar) : "memory");
    }

    // ---- build coefficient tables while the TMA flies ----
    const float Lu = Lu_p[0];
    const float a0 = alpha[0];
    {
        float negLu3 = -(Lu * Lu * Lu);
        float ssv = 0.25f / negLu3 + a0 * 3.0f / Lu;
        float sdv = 0.50f / negLu3 + a0 * 3.0f / Lu;
        u64 ss2 = pk2(ssv, ssv), sd2 = pk2(sdv, sdv);
        for (int k = t; k < 160; k += 256) {
            float4 bias; u64 sl;
            if (k < 136) {
                int chunk = UPPER_TAB_C[k];
                int ei = chunk >> 3, jb = (chunk & 7) * 4;
                bias.x = (jb + 0 > ei) ? -3e38f : Lu;
                bias.y = (jb + 1 > ei) ? -3e38f : Lu;
                bias.z = (jb + 2 > ei) ? -3e38f : Lu;
                bias.w = (jb + 3 > ei) ? -3e38f : Lu;
                sl = ((ei < 16) == (jb < 16)) ? ss2 : sd2;
            } else {
                bias = make_float4(Lu, Lu, Lu, Lu);   // dummy -> zero contribution
                sl = ss2;
            }
            s_bias[k]  = bias;
            s_slope[k] = sl;
        }
    }
    if (t < NNUC) s_L[t] = Lchi[type_idx[t]];
    if (t >= 32 && t < 32 + 28) {
        int k = t - 32, pr = k / 7, q = k % 7;
        int ty0 = type_idx[2 * pr], ty1 = type_idx[2 * pr + 1];
        s_hi2[pr][q] = pk2(beta[ty0 * NCHI + q + 1] * 0.125f,
                           beta[ty1 * NCHI + q + 1] * 0.125f);
    }
    if (t >= 64 && t < 68) {
        int pr = t - 64;
        int m0 = 2 * pr, m1 = m0 + 1;
        int ty0 = type_idx[m0], ty1 = type_idx[m1];
        float La = Lchi[ty0], Lb = Lchi[ty1];
        float b00 = beta[ty0 * NCHI], b01 = beta[ty1 * NCHI];
        float lin0 = (-Zarr[m0] / (-(La * La * La)) + b00 * 3.0f / La) * 0.125f;
        float lin1 = (-Zarr[m1] / (-(Lb * Lb * Lb)) + b01 * 3.0f / Lb) * 0.125f;
        s_c02[pr]  = pk2(b00 * 0.125f, b01 * 0.125f);
        s_lin2[pr] = pk2(lin0, lin1);
    }

    // alpha packed in registers (per-thread)
    u64 a2[NU];
    #pragma unroll
    for (int q = 0; q < NU; ++q) { float a = alpha[q]; a2[q] = pk2(a, a); }

    // my 5 elec chunk ids (slot k = lane + 32*g, g=0..4; >=136 -> dummy 0)
    int myChunk[5];
    #pragma unroll
    for (int g = 0; g < 5; ++g) {
        int k = lane + 32 * g;
        myChunk[g] = (k < 136) ? (int)UPPER_TAB_C[k] : 0;
    }

    __syncthreads();   // coefficient tables ready

    // ---- wait for TMA data (parity 0) ----
    asm volatile(
        "{\n\t.reg .pred P;\n\t"
        "WAIT_%=:\n\t"
        "mbarrier.try_wait.parity.acquire.cta.shared::cta.b64 P, [%0], 0, 0x989680;\n\t"
        "@P bra.uni DONE_%=;\n\t"
        "bra.uni WAIT_%=;\n\t"
        "DONE_%=:\n\t}"
        :: "r"(mbar) : "memory");

    // ================= compute: warp w owns walker g0+w =================
    u64 acc2 = pk2(0.f, 0.f);

    // -- nuc groups: slots s = lane, lane+32 (all nuc) --
    {
        const int pr0 = (lane & 1) * 2;
        const int mb  = (lane & 1) * 4;
        const float L0 = s_L[mb], L1 = s_L[mb + 1], L2 = s_L[mb + 2], L3 = s_L[mb + 3];
        const char* nbase = s_nuc + w * 1024;
        #pragma unroll
        for (int g = 0; g < 2; ++g) {
            int s = lane + 32 * g;
            float4 v = *reinterpret_cast<const float4*>(nbase + s * 16);
            float rc0 = fminf(v.x, L0), rc1 = fminf(v.y, L1);
            float rc2 = fminf(v.z, L2), rc3 = fminf(v.w, L3);
            u64 rA = pk2(rc0, rc1), rB = pk2(rc2, rc3);
            u64 dA = pk2(rc0 - L0, rc1 - L1), dB = pk2(rc2 - L2, rc3 - L3);
            u64 envA = mul2(mul2(dA, dA), dA);
            u64 envB = mul2(mul2(dB, dB), dB);
            u64 pA = s_hi2[pr0][6], pB = s_hi2[pr0 + 1][6];
            #pragma unroll
            for (int q = 5; q >= 0; --q) {
                pA = fma2(pA, rA, s_hi2[pr0][q]);
                pB = fma2(pB, rB, s_hi2[pr0 + 1][q]);
            }
            u64 rA2 = mul2(rA, rA), rB2 = mul2(rB, rB);
            pA = fma2(pA, rA2, fma2(s_lin2[pr0],     rA, s_c02[pr0]));
            pB = fma2(pB, rB2, fma2(s_lin2[pr0 + 1], rB, s_c02[pr0 + 1]));
            acc2 = fma2(envA, pA, acc2);
            acc2 = fma2(envB, pB, acc2);
        }
    }

    // -- elec groups: slots k = lane + 32*g, g=0..4 --
    {
        const char* ebase = s_elec + w * 4096;
        #pragma unroll
        for (int g = 0; g < 5; ++g) {
            int k = lane + 32 * g;
            float4 v   = *reinterpret_cast<const float4*>(ebase + myChunk[g] * 16);
            float4 bb  = s_bias[k];
            u64 slope2 = s_slope[k];
            float rc0 = fmaxf(fminf(v.x, Lu), bb.x);
            float rc1 = fmaxf(fminf(v.y, Lu), bb.y);
            float rc2 = fmaxf(fminf(v.z, Lu), bb.z);
            float rc3 = fmaxf(fminf(v.w, Lu), bb.w);
            u64 rA = pk2(rc0, rc1), rB = pk2(rc2, rc3);
            u64 dA = pk2(rc0 - Lu, rc1 - Lu), dB = pk2(rc2 - Lu, rc3 - Lu);
            u64 envA = mul2(mul2(dA, dA), dA);
            u64 envB = mul2(mul2(dB, dB), dB);
            u64 pA = a2[NU - 1], pB = a2[NU - 1];
            #pragma unroll
            for (int q = NU - 2; q >= 1; --q) {
                pA = fma2(pA, rA, a2[q]);
                pB = fma2(pB, rB, a2[q]);
            }
            u64 rA2 = mul2(rA, rA), rB2 = mul2(rB, rB);
            pA = fma2(pA, rA2, fma2(slope2, rA, a2[0]));
            pB = fma2(pB, rB2, fma2(slope2, rB, a2[0]));
            acc2 = fma2(envA, pA, acc2);
            acc2 = fma2(envB, pB, acc2);
        }
    }

    // ---- warp reduce, lane 0 writes this walker's result ----
    float aLo, aHi;
    upk2(acc2, aLo, aHi);
    float acc = aLo + aHi;
    #pragma unroll
    for (int off = 16; off > 0; off >>= 1)
        acc += __shfl_down_sync(0xffffffffu, acc, off);
    if (lane == 0) out[g0 + w] = acc;
}

extern "C" void kernel_launch(void* const* d_in, const int* in_sizes, int n_in,
                              void* d_out, int out_size)
{
    const char* elec  = (const char*)d_in[0];
    const char* nuc   = (const char*)d_in[1];
    const float* alpha = (const float*)d_in[2];
    const float* beta  = (const float*)d_in[3];
    const float* Z     = (const float*)d_in[4];
    const float* Lchi  = (const float*)d_in[5];
    const float* Lu    = (const float*)d_in[6];
    const int*   tidx  = (const int*)  d_in[7];
    float* out = (float*)d_out;

    int B = in_sizes[1] / (32 * NNUC);   // 4096

    jastrow_kernel<<<B / WPB, 256>>>(elec, nuc, alpha, beta, Z, Lchi, Lu, tidx, out);
}

// round 11
// speedup vs baseline: 1.1982x; 1.1923x over previous
#include <cuda_runtime.h>
#include <cuda_bf16.h>

#define NE    32
#define NNUC  8
#define NCHI  8
#define NU    8
#define WPB   8      // walkers per block (2 warps each -> 512 threads)

typedef unsigned long long u64;

// ---- f32x2 packed helpers (Blackwell) ----
__device__ __forceinline__ u64 pk2(float lo, float hi) {
    u64 r; asm("mov.b64 %0, {%1, %2};" : "=l"(r) : "f"(lo), "f"(hi)); return r;
}
__device__ __forceinline__ void upk2(u64 v, float& lo, float& hi) {
    asm("mov.b64 {%0, %1}, %2;" : "=f"(lo), "=f"(hi) : "l"(v));
}
__device__ __forceinline__ u64 fma2(u64 a, u64 b, u64 c) {
    u64 d; asm("fma.rn.f32x2 %0, %1, %2, %3;" : "=l"(d) : "l"(a), "l"(b), "l"(c)); return d;
}
__device__ __forceinline__ u64 mul2(u64 a, u64 b) {
    u64 d; asm("mul.rn.f32x2 %0, %1, %2;" : "=l"(d) : "l"(a), "l"(b)); return d;
}

// Flat float4-chunk indices (i*8 + c) of the 136 chunks touching the strict
// upper triangle of the 32x32 elec matrix.
static __device__ const unsigned char UPPER_TAB[136] = {
    0,1,2,3,4,5,6,7,
    8,9,10,11,12,13,14,15,
    16,17,18,19,20,21,22,23,
    25,26,27,28,29,30,31,
    33,34,35,36,37,38,39,
    41,42,43,44,45,46,47,
    49,50,51,52,53,54,55,
    58,59,60,61,62,63,
    66,67,68,69,70,71,
    74,75,76,77,78,79,
    82,83,84,85,86,87,
    91,92,93,94,95,
    99,100,101,102,103,
    107,108,109,110,111,
    115,116,117,118,119,
    124,125,126,127,
    132,133,134,135,
    140,141,142,143,
    148,149,150,151,
    157,158,159,
    165,166,167,
    173,174,175,
    181,182,183,
    190,191,
    198,199,
    206,207,
    214,215,
    223,
    231,
    239,
    247
};

__global__ __launch_bounds__(512, 2)
void jastrow_kernel(
    const float4* __restrict__ elec4,   // [B, 256]
    const float4* __restrict__ nuc4,    // [B, 64]
    const float* __restrict__ alpha,    // [8]
    const float* __restrict__ beta,     // [3, 8]
    const float* __restrict__ Zarr,     // [8]
    const float* __restrict__ Lchi,     // [3]
    const float* __restrict__ Lu_p,     // [1]
    const int*   __restrict__ type_idx, // [8]
    float* __restrict__ out)            // [B]
{
    __shared__ u64 s_ss2, s_sd2;        // slope same/diff packed
    __shared__ u64 s_hi2[4][NCHI - 1];  // beta[1..7]/8 for nucleus pair (2p,2p+1)
    __shared__ u64 s_c02[4];            // beta0/8 pair-packed
    __shared__ u64 s_lin2[4];           // lin/8 pair-packed
    __shared__ float s_L[NNUC];
    __shared__ float s_Lu;
    __shared__ int  s_info[136];        // chunk | mask<<8 | same<<12
    __shared__ float s_part[16];

    const int t    = threadIdx.x;
    const int lane = t & 31;
    const int warp = t >> 5;            // 0..15
    const int wk   = warp >> 1;         // walker in block 0..7
    const int b    = blockIdx.x * WPB + wk;
    const int l    = (warp & 1) * 32 + lane;   // 0..63 within walker team

    // ---- setup ----
    if (t < NNUC) s_L[t] = Lchi[type_idx[t]];
    if (t == 16) {
        float Lu = Lu_p[0];
        s_Lu = Lu;
        float a0 = alpha[0];
        float negL3 = -(Lu * Lu * Lu);
        float ss = 0.25f / negL3 + a0 * 3.0f / Lu;
        float sd = 0.50f / negL3 + a0 * 3.0f / Lu;
        s_ss2 = pk2(ss, ss);
        s_sd2 = pk2(sd, sd);
    }
    if (t >= 32 && t < 32 + 28) {       // pack beta high coefs per nucleus pair
        int k = t - 32, pr = k / 7, q = k % 7;
        int m0 = 2 * pr, m1 = m0 + 1;
        int ty0 = type_idx[m0], ty1 = type_idx[m1];
        s_hi2[pr][q] = pk2(beta[ty0 * NCHI + q + 1] * 0.125f,
                           beta[ty1 * NCHI + q + 1] * 0.125f);
    }
    if (t >= 64 && t < 68) {            // c0 and lin pair-packed
        int pr = t - 64;
        int m0 = 2 * pr, m1 = m0 + 1;
        int ty0 = type_idx[m0], ty1 = type_idx[m1];
        float L0 = Lchi[ty0], L1 = Lchi[ty1];
        float b00 = beta[ty0 * NCHI], b01 = beta[ty1 * NCHI];
        float lin0 = (-Zarr[m0] / (-(L0 * L0 * L0)) + b00 * 3.0f / L0) * 0.125f;
        float lin1 = (-Zarr[m1] / (-(L1 * L1 * L1)) + b01 * 3.0f / L1) * 0.125f;
        s_c02[pr]  = pk2(b00 * 0.125f, b01 * 0.125f);
        s_lin2[pr] = pk2(lin0, lin1);
    }
    if (t >= 120 && t < 120 + 136) {    // info table
        int k = t - 120;
        int v = UPPER_TAB[k];
        int i = v >> 3, jb = (v & 7) * 4;
        int mask = 0;
        #pragma unroll
        for (int p = 0; p < 4; ++p) if (jb + p > i) mask |= 1 << p;
        int same = ((i < 16) == (jb < 16)) ? 1 : 0;
        s_info[k] = v | (mask << 8) | (same << 12);
    }

    // ---- alpha coefficients straight into registers (no smem in hot path) ----
    u64 a2[NU];
    #pragma unroll
    for (int q = 0; q < NU; ++q) { float a = alpha[q]; a2[q] = pk2(a, a); }

    __syncthreads();

    // ---- issue all loads up front ----
    float4 rn = __ldg(nuc4 + (size_t)b * 64 + l);

    const float4* erow = elec4 + (size_t)b * 256;
    int info0 = s_info[l];
    int info1 = s_info[l + 64];
    float4 e0 = __ldg(erow + (info0 & 255));
    float4 e1 = __ldg(erow + (info1 & 255));
    float4 e2;
    int info2 = 0;
    const bool has2 = (l < 8);
    if (has2) { info2 = s_info[128 + l]; e2 = __ldg(erow + (info2 & 255)); }

    // hoist slopes once
    const u64 ss2 = s_ss2, sd2 = s_sd2;

    u64 acc2 = pk2(0.f, 0.f);

    // ---- e-N chunk: nuclei mb..mb+3, coef pairs pr0, pr0+1 (smem coefs) ----
    {
        const int pr0 = (l & 1) * 2;
        const int mb  = (l & 1) * 4;
        float d0 = fminf(rn.x - s_L[mb + 0], 0.f);
        float d1 = fminf(rn.y - s_L[mb + 1], 0.f);
        float d2 = fminf(rn.z - s_L[mb + 2], 0.f);
        float d3 = fminf(rn.w - s_L[mb + 3], 0.f);
        u64 rA = pk2(rn.x, rn.y), rB = pk2(rn.z, rn.w);
        u64 dA = pk2(d0, d1),     dB = pk2(d2, d3);
        u64 envA = mul2(mul2(dA, dA), dA);
        u64 envB = mul2(mul2(dB, dB), dB);
        u64 pA = s_hi2[pr0][6];
        u64 pB = s_hi2[pr0 + 1][6];
        #pragma unroll
        for (int q = 5; q >= 0; --q) {
            pA = fma2(pA, rA, s_hi2[pr0][q]);
            pB = fma2(pB, rB, s_hi2[pr0 + 1][q]);
        }
        u64 rA2 = mul2(rA, rA), rB2 = mul2(rB, rB);
        pA = fma2(pA, rA2, fma2(s_lin2[pr0],     rA, s_c02[pr0]));
        pB = fma2(pB, rB2, fma2(s_lin2[pr0 + 1], rB, s_c02[pr0 + 1]));
        acc2 = fma2(envA, pA, acc2);
        acc2 = fma2(envB, pB, acc2);
    }

    // ---- e-e chunks: pure-register Horner ----
    const float Lu = s_Lu;

    auto do_chunk = [&](int info, const float4& v) {
        int mask = (info >> 8) & 15;
        u64 slope2 = (info & 0x1000) ? ss2 : sd2;
        float d0 = (mask & 1) ? fminf(v.x - Lu, 0.f) : 0.f;
        float d1 = (mask & 2) ? fminf(v.y - Lu, 0.f) : 0.f;
        float d2 = (mask & 4) ? fminf(v.z - Lu, 0.f) : 0.f;
        float d3 = (mask & 8) ? fminf(v.w - Lu, 0.f) : 0.f;
        u64 rA = pk2(v.x, v.y), rB = pk2(v.z, v.w);
        u64 dA = pk2(d0, d1),   dB = pk2(d2, d3);
        u64 envA = mul2(mul2(dA, dA), dA);
        u64 envB = mul2(mul2(dB, dB), dB);
        u64 pA = a2[NU - 1];
        u64 pB = a2[NU - 1];
        #pragma unroll
        for (int q = NU - 2; q >= 1; --q) {
            pA = fma2(pA, rA, a2[q]);
            pB = fma2(pB, rB, a2[q]);
        }
        u64 rA2 = mul2(rA, rA), rB2 = mul2(rB, rB);
        pA = fma2(pA, rA2, fma2(slope2, rA, a2[0]));
        pB = fma2(pB, rB2, fma2(slope2, rB, a2[0]));
        acc2 = fma2(envA, pA, acc2);
        acc2 = fma2(envB, pB, acc2);
    };

    do_chunk(info0, e0);
    do_chunk(info1, e1);
    if (has2) do_chunk(info2, e2);

    // ---- reduce ----
    float aLo, aHi;
    upk2(acc2, aLo, aHi);
    float acc = aLo + aHi;
    #pragma unroll
    for (int off = 16; off > 0; off >>= 1)
        acc += __shfl_down_sync(0xffffffffu, acc, off);
    if (lane == 0) s_part[warp] = acc;
    __syncthreads();
    if (t < WPB)
        out[blockIdx.x * WPB + t] = s_part[2 * t] + s_part[2 * t + 1];
}

extern "C" void kernel_launch(void* const* d_in, const int* in_sizes, int n_in,
                              void* d_out, int out_size)
{
    const float4* elec  = (const float4*)d_in[0];
    const float4* nuc   = (const float4*)d_in[1];
    const float* alpha  = (const float*)d_in[2];
    const float* beta   = (const float*)d_in[3];
    const float* Z      = (const float*)d_in[4];
    const float* Lchi   = (const float*)d_in[5];
    const float* Lu     = (const float*)d_in[6];
    const int*   tidx   = (const int*)  d_in[7];
    float* out = (float*)d_out;

    int B = in_sizes[1] / (NE * NNUC);   // 4096

    jastrow_kernel<<<B / WPB, 512>>>(elec, nuc, alpha, beta, Z, Lchi, Lu, tidx, out);
}